// round 4
// baseline (speedup 1.0000x reference)
#include <cuda_runtime.h>
#include <math.h>
#include <float.h>

// ---------------- problem constants ----------------
#define NN   2048
#define DIN  512
#define HID  256
#define NH   4
#define TOPK 6      // k+1

// ---------------- device scratch (static, no allocs) ----------------
__device__ float g_sqU[NN];
__device__ float g_XnF[NN*DIN];
__device__ float g_simU[NN*NN];   // reused as att scratch for user GAT
__device__ float g_simF[NN*NN];   // reused as att scratch for food GAT
__device__ int   g_tidxU[NN*TOPK];
__device__ float g_tvalU[NN*TOPK];
__device__ int   g_tidxF[NN*TOPK];
__device__ float g_tvalF[NN*TOPK];
__device__ unsigned char g_maskU[NN*NN];
__device__ unsigned char g_maskF[NN*NN];
__device__ float g_WcatU[DIN*NH*HID];
__device__ float g_WcatF[DIN*NH*HID];
__device__ float g_WhU[NN*NH*HID];
__device__ float g_WhF[NN*NH*HID];
__device__ float g_s1U[NH*NN];
__device__ float g_s2U[NH*NN];
__device__ float g_s1F[NH*NN];
__device__ float g_s2F[NH*NN];
__device__ float g_hidU[NN*NH*HID];
__device__ float g_hidF[NN*NH*HID];
__device__ float g_WhoU[NN*HID];
__device__ float g_WhoF[NN*HID];
__device__ float g_s1oU[NN];
__device__ float g_s2oU[NN];
__device__ float g_s1oF[NN];
__device__ float g_s2oF[NN];
__device__ float g_embU[NN*HID];
__device__ float g_embF[NN*HID];
__device__ float g_pair[NN*512];
__device__ float g_act0[NN*512];
__device__ float g_act1[NN*256];
__device__ float g_act2[NN*128];

// ---------------- SGEMM: 128x128x16 tile, 256 thr, 8x8 micro, fp32 ----------------
// TB=false: C[M,Nn] = A[M,K] * B[K,Nn]    (B row-major, leading dim ldb)
// TB=true : C[M,Nn] = A[M,K] * B[Nn,K]^T  (B row-major [Nn,K], leading dim ldb)
// EP: 0 none; 1 negd2 = -((sq[row]+sq[col]) - 2*acc); 2 bias+relu; 3 elu
#define BM 128
#define BN 128
#define BKK 16

template<bool TB, int EP>
__global__ void sgemm(const float* __restrict__ A, const float* __restrict__ B,
                      float* __restrict__ C, int M, int Nn, int Kk,
                      int lda, int ldb, int ldc,
                      const float* __restrict__ sq, const float* __restrict__ bias)
{
    __shared__ float As[BKK][BM+4];
    __shared__ float Bs[BKK][BN+4];
    const int tid = threadIdx.x;
    const int m0 = blockIdx.y * BM;
    const int n0 = blockIdx.x * BN;
    const int tm = (tid / 16) * 8;
    const int tn = (tid % 16) * 8;

    float acc[8][8];
#pragma unroll
    for (int i = 0; i < 8; i++)
#pragma unroll
        for (int j = 0; j < 8; j++) acc[i][j] = 0.f;

    for (int k0 = 0; k0 < Kk; k0 += BKK) {
#pragma unroll
        for (int it = 0; it < 2; it++) {
            int q = tid + it * 256;
            int r = q >> 2;
            int c4 = (q & 3) * 4;
            float4 v = *(const float4*)(A + (size_t)(m0 + r) * lda + k0 + c4);
            As[c4+0][r] = v.x; As[c4+1][r] = v.y; As[c4+2][r] = v.z; As[c4+3][r] = v.w;
        }
        if (!TB) {
#pragma unroll
            for (int it = 0; it < 2; it++) {
                int q = tid + it * 256;
                int r = q >> 5;
                int c4 = (q & 31) * 4;
                float4 v = *(const float4*)(B + (size_t)(k0 + r) * ldb + n0 + c4);
                Bs[r][c4+0] = v.x; Bs[r][c4+1] = v.y; Bs[r][c4+2] = v.z; Bs[r][c4+3] = v.w;
            }
        } else {
#pragma unroll
            for (int it = 0; it < 2; it++) {
                int q = tid + it * 256;
                int r = q >> 2;
                int c4 = (q & 3) * 4;
                float4 v = *(const float4*)(B + (size_t)(n0 + r) * ldb + k0 + c4);
                Bs[c4+0][r] = v.x; Bs[c4+1][r] = v.y; Bs[c4+2][r] = v.z; Bs[c4+3][r] = v.w;
            }
        }
        __syncthreads();

#pragma unroll
        for (int k = 0; k < BKK; k++) {
            float a[8], b[8];
#pragma unroll
            for (int j = 0; j < 8; j++) a[j] = As[k][tm + j];
#pragma unroll
            for (int j = 0; j < 8; j++) b[j] = Bs[k][tn + j];
#pragma unroll
            for (int i = 0; i < 8; i++)
#pragma unroll
                for (int j = 0; j < 8; j++) acc[i][j] = fmaf(a[i], b[j], acc[i][j]);
        }
        __syncthreads();
    }

#pragma unroll
    for (int i = 0; i < 8; i++) {
        int row = m0 + tm + i;
#pragma unroll
        for (int j = 0; j < 8; j++) {
            int col = n0 + tn + j;
            float v = acc[i][j];
            if (EP == 1) v = -((sq[row] + sq[col]) - 2.f * v);
            if (EP == 2) { v += bias[col]; v = fmaxf(v, 0.f); }
            if (EP == 3) v = (v > 0.f) ? v : expm1f(v);
            C[(size_t)row * ldc + col] = v;
        }
    }
}

// ---------------- row reductions ----------------
__global__ void rowsum_sq(const float* __restrict__ X, float* __restrict__ out, int D)
{
    int i = blockIdx.x, tid = threadIdx.x;
    float s = 0.f;
    for (int j = tid; j < D; j += blockDim.x) { float v = X[(size_t)i*D + j]; s = fmaf(v, v, s); }
    __shared__ float r[256];
    r[tid] = s; __syncthreads();
    for (int st = blockDim.x >> 1; st > 0; st >>= 1) { if (tid < st) r[tid] += r[tid + st]; __syncthreads(); }
    if (tid == 0) out[i] = r[0];
}

__global__ void normalize_rows(const float* __restrict__ X, float* __restrict__ Y, int D)
{
    int i = blockIdx.x, tid = threadIdx.x;
    float s = 0.f;
    for (int j = tid; j < D; j += blockDim.x) { float v = X[(size_t)i*D + j]; s = fmaf(v, v, s); }
    __shared__ float r[256];
    r[tid] = s; __syncthreads();
    for (int st = blockDim.x >> 1; st > 0; st >>= 1) { if (tid < st) r[tid] += r[tid + st]; __syncthreads(); }
    float nrm = sqrtf(r[0]);
    for (int j = tid; j < D; j += blockDim.x) Y[(size_t)i*D + j] = X[(size_t)i*D + j] / nrm;
}

// ---------------- brute-force top-6 per row: one warp, 6 argmax passes ----------------
__global__ void top6_bf(const float* __restrict__ S, int* __restrict__ outIdx,
                        float* __restrict__ outVal)
{
    int row = blockIdx.x;
    int lane = threadIdx.x;            // 32 threads
    const float* Sr = S + (size_t)row * NN;
    int chosen[TOPK];
#pragma unroll
    for (int t = 0; t < TOPK; t++) {
        float bv = -FLT_MAX; int bi = 0x7FFFFFFF;
        for (int j = lane; j < NN; j += 32) {
            bool used = false;
#pragma unroll
            for (int u = 0; u < TOPK; u++) if (u < t) used |= (chosen[u] == j);
            if (!used) {
                float x = Sr[j];
                if (x > bv || (x == bv && j < bi)) { bv = x; bi = j; }
            }
        }
        for (int off = 16; off > 0; off >>= 1) {
            float ov = __shfl_down_sync(0xFFFFFFFFu, bv, off);
            int   oi = __shfl_down_sync(0xFFFFFFFFu, bi, off);
            if (ov > bv || (ov == bv && oi < bi)) { bv = ov; bi = oi; }
        }
        bi = __shfl_sync(0xFFFFFFFFu, bi, 0);
        bv = __shfl_sync(0xFFFFFFFFu, bv, 0);
        chosen[t] = bi;
        if (lane == 0) { outIdx[row*TOPK + t] = bi; outVal[row*TOPK + t] = bv; }
    }
}

// ---------------- adjacency mask build ----------------
__global__ void clear_masks()
{
    int i = blockIdx.x * blockDim.x + threadIdx.x;   // NN*NN/4 words
    ((unsigned int*)g_maskU)[i] = 0u;
    ((unsigned int*)g_maskF)[i] = 0u;
}

__global__ void mark_kernel(const int* __restrict__ idx, const float* __restrict__ val,
                            unsigned char* __restrict__ mask, int needPos)
{
    int i = blockIdx.x * blockDim.x + threadIdx.x;
    if (i >= NN) return;
#pragma unroll
    for (int t = 0; t < TOPK; t++) {
        int j = idx[i*TOPK + t];
        if (j == i) continue;
        if (needPos && !(val[i*TOPK + t] > 0.f)) continue;
        mask[(size_t)i*NN + j] = 1;
        mask[(size_t)j*NN + i] = 1;
    }
}

// ---------------- GAT helper kernels ----------------
// W [NH][DIN][HID] -> Wcat [DIN][NH*HID]
__global__ void repack_W(const float* __restrict__ W, float* __restrict__ Wcat)
{
    int i = blockIdx.x * blockDim.x + threadIdx.x;
    if (i >= DIN*NH*HID) return;
    int d = i / (NH*HID);
    int r = i % (NH*HID);
    int h = r / HID;
    int f = r % HID;
    Wcat[i] = W[(size_t)h*DIN*HID + (size_t)d*HID + f];
}

// s1[h*NN+i] = dot(Wh[i, h*256:+256], a[h*512:+256]); s2 second half
__global__ void s1s2_kernel(const float* __restrict__ Wh, int rowStride,
                            const float* __restrict__ a,
                            float* __restrict__ s1, float* __restrict__ s2)
{
    int i = blockIdx.x, h = blockIdx.y, f = threadIdx.x;   // 256 threads
    float w = Wh[(size_t)i*rowStride + h*HID + f];
    float v1 = w * a[h*2*HID + f];
    float v2 = w * a[h*2*HID + HID + f];
    __shared__ float r1[256], r2[256];
    r1[f] = v1; r2[f] = v2; __syncthreads();
    for (int st = 128; st > 0; st >>= 1) {
        if (f < st) { r1[f] += r1[f+st]; r2[f] += r2[f+st]; }
        __syncthreads();
    }
    if (f == 0) { s1[h*NN + i] = r1[0]; s2[h*NN + i] = r2[0]; }
}

// ---------------- dense masked softmax attention row ----------------
// att[i,j] = softmax_j( mask ? leaky(s1[i]+s2[j]) : -inf )
__global__ void att_build(const unsigned char* __restrict__ mask,
                          const float* __restrict__ s1, const float* __restrict__ s2,
                          int h, float* __restrict__ att)
{
    int i = blockIdx.x, tid = threadIdx.x;   // 256 threads
    const unsigned char* mrow = mask + (size_t)i*NN;
    float s1i = s1[h*NN + i];
    __shared__ float red[256];

    float mx = -FLT_MAX;
    for (int j = tid; j < NN; j += 256) {
        if (mrow[j]) {
            float e = s1i + s2[h*NN + j];
            e = (e >= 0.f) ? e : 0.2f * e;
            mx = fmaxf(mx, e);
        }
    }
    red[tid] = mx; __syncthreads();
    for (int st = 128; st > 0; st >>= 1) { if (tid < st) red[tid] = fmaxf(red[tid], red[tid+st]); __syncthreads(); }
    mx = red[0];
    __syncthreads();

    float sm = 0.f;
    for (int j = tid; j < NN; j += 256) {
        float v = 0.f;
        if (mrow[j]) {
            float e = s1i + s2[h*NN + j];
            e = (e >= 0.f) ? e : 0.2f * e;
            v = expf(e - mx);
        }
        att[(size_t)i*NN + j] = v;
        sm += v;
    }
    red[tid] = sm; __syncthreads();
    for (int st = 128; st > 0; st >>= 1) { if (tid < st) red[tid] += red[tid+st]; __syncthreads(); }
    float inv = 1.f / red[0];
    __syncthreads();
    for (int j = tid; j < NN; j += 256)
        att[(size_t)i*NN + j] *= inv;
}

// ---------------- MLP pieces ----------------
__global__ void concat_kernel()
{
    int i = blockIdx.x, c = threadIdx.x;   // 512 threads
    g_pair[(size_t)i*512 + c] = (c < HID) ? g_embU[(size_t)i*HID + c]
                                          : g_embF[(size_t)i*HID + (c - HID)];
}

__global__ void mlp_final_kernel(const float* __restrict__ act, const float* __restrict__ W,
                                 const float* __restrict__ b, float* __restrict__ out)
{
    int i = blockIdx.x, tid = threadIdx.x;   // 128 threads
    float v = act[(size_t)i*128 + tid] * W[tid];
    __shared__ float r[128];
    r[tid] = v; __syncthreads();
    for (int st = 64; st > 0; st >>= 1) { if (tid < st) r[tid] += r[tid+st]; __syncthreads(); }
    if (tid == 0) out[i] = r[0] + b[0];
}

// ---------------- host launch ----------------
template <typename T>
static T* sym(const void* s)
{
    void* p = nullptr;
    cudaGetSymbolAddress(&p, s);
    return (T*)p;
}

extern "C" void kernel_launch(void* const* d_in, const int* in_sizes, int n_in,
                              void* d_out, int out_size)
{
    const float* user_nodes = (const float*)d_in[0];
    const float* food_nodes = (const float*)d_in[1];
    const float* user_W_h   = (const float*)d_in[2];
    const float* user_a_h   = (const float*)d_in[3];
    const float* user_W_o   = (const float*)d_in[4];
    const float* user_a_o   = (const float*)d_in[5];
    const float* food_W_h   = (const float*)d_in[6];
    const float* food_a_h   = (const float*)d_in[7];
    const float* food_W_o   = (const float*)d_in[8];
    const float* food_a_o   = (const float*)d_in[9];
    const float* mlp_W0 = (const float*)d_in[10];
    const float* mlp_b0 = (const float*)d_in[11];
    const float* mlp_W1 = (const float*)d_in[12];
    const float* mlp_b1 = (const float*)d_in[13];
    const float* mlp_W2 = (const float*)d_in[14];
    const float* mlp_b2 = (const float*)d_in[15];
    const float* mlp_W3 = (const float*)d_in[16];
    const float* mlp_b3 = (const float*)d_in[17];
    float* out = (float*)d_out;

    float* pSqU   = sym<float>(g_sqU);
    float* pXnF   = sym<float>(g_XnF);
    float* pSimU  = sym<float>(g_simU);
    float* pSimF  = sym<float>(g_simF);
    int*   pTidxU = sym<int>(g_tidxU);
    float* pTvalU = sym<float>(g_tvalU);
    int*   pTidxF = sym<int>(g_tidxF);
    float* pTvalF = sym<float>(g_tvalF);
    unsigned char* pMaskU = sym<unsigned char>(g_maskU);
    unsigned char* pMaskF = sym<unsigned char>(g_maskF);
    float* pWcatU = sym<float>(g_WcatU);
    float* pWcatF = sym<float>(g_WcatF);
    float* pWhU  = sym<float>(g_WhU);
    float* pWhF  = sym<float>(g_WhF);
    float* pS1U  = sym<float>(g_s1U);
    float* pS2U  = sym<float>(g_s2U);
    float* pS1F  = sym<float>(g_s1F);
    float* pS2F  = sym<float>(g_s2F);
    float* pHidU = sym<float>(g_hidU);
    float* pHidF = sym<float>(g_hidF);
    float* pWhoU = sym<float>(g_WhoU);
    float* pWhoF = sym<float>(g_WhoF);
    float* pS1oU = sym<float>(g_s1oU);
    float* pS2oU = sym<float>(g_s2oU);
    float* pS1oF = sym<float>(g_s1oF);
    float* pS2oF = sym<float>(g_s2oF);
    float* pEmbU = sym<float>(g_embU);
    float* pEmbF = sym<float>(g_embF);
    float* pPair = sym<float>(g_pair);
    float* pAct0 = sym<float>(g_act0);
    float* pAct1 = sym<float>(g_act1);
    float* pAct2 = sym<float>(g_act2);

    // ---- graph build ----
    rowsum_sq<<<NN, 256>>>(user_nodes, pSqU, DIN);
    sgemm<true, 1><<<dim3(NN/BN, NN/BM), 256>>>(user_nodes, user_nodes, pSimU,
                                                NN, NN, DIN, DIN, DIN, NN, pSqU, nullptr);
    top6_bf<<<NN, 32>>>(pSimU, pTidxU, pTvalU);

    normalize_rows<<<NN, 256>>>(food_nodes, pXnF, DIN);
    sgemm<true, 0><<<dim3(NN/BN, NN/BM), 256>>>(pXnF, pXnF, pSimF,
                                                NN, NN, DIN, DIN, DIN, NN, nullptr, nullptr);
    top6_bf<<<NN, 32>>>(pSimF, pTidxF, pTvalF);

    clear_masks<<<(NN*NN/4)/256, 256>>>();
    mark_kernel<<<(NN+255)/256, 256>>>(pTidxU, pTvalU, pMaskU, 0);
    mark_kernel<<<(NN+255)/256, 256>>>(pTidxF, pTvalF, pMaskF, 1);

    // ---- user GAT (dense attention; att scratch = g_simU) ----
    repack_W<<<(DIN*NH*HID + 255)/256, 256>>>(user_W_h, pWcatU);
    sgemm<false, 0><<<dim3((NH*HID)/BN, NN/BM), 256>>>(user_nodes, pWcatU, pWhU,
                                                       NN, NH*HID, DIN, DIN, NH*HID, NH*HID,
                                                       nullptr, nullptr);
    s1s2_kernel<<<dim3(NN, NH), 256>>>(pWhU, NH*HID, user_a_h, pS1U, pS2U);
    for (int h = 0; h < NH; h++) {
        att_build<<<NN, 256>>>(pMaskU, pS1U, pS2U, h, pSimU);
        sgemm<false, 3><<<dim3(HID/BN, NN/BM), 256>>>(pSimU, pWhU + h*HID, pHidU + h*HID,
                                                      NN, HID, NN, NN, NH*HID, NH*HID,
                                                      nullptr, nullptr);
    }
    sgemm<false, 0><<<dim3(HID/BN, NN/BM), 256>>>(pHidU, user_W_o, pWhoU,
                                                  NN, HID, NH*HID, NH*HID, HID, HID,
                                                  nullptr, nullptr);
    s1s2_kernel<<<dim3(NN, 1), 256>>>(pWhoU, HID, user_a_o, pS1oU, pS2oU);
    att_build<<<NN, 256>>>(pMaskU, pS1oU, pS2oU, 0, pSimU);
    sgemm<false, 3><<<dim3(HID/BN, NN/BM), 256>>>(pSimU, pWhoU, pEmbU,
                                                  NN, HID, NN, NN, HID, HID,
                                                  nullptr, nullptr);

    // ---- food GAT (dense attention; att scratch = g_simF) ----
    repack_W<<<(DIN*NH*HID + 255)/256, 256>>>(food_W_h, pWcatF);
    sgemm<false, 0><<<dim3((NH*HID)/BN, NN/BM), 256>>>(food_nodes, pWcatF, pWhF,
                                                       NN, NH*HID, DIN, DIN, NH*HID, NH*HID,
                                                       nullptr, nullptr);
    s1s2_kernel<<<dim3(NN, NH), 256>>>(pWhF, NH*HID, food_a_h, pS1F, pS2F);
    for (int h = 0; h < NH; h++) {
        att_build<<<NN, 256>>>(pMaskF, pS1F, pS2F, h, pSimF);
        sgemm<false, 3><<<dim3(HID/BN, NN/BM), 256>>>(pSimF, pWhF + h*HID, pHidF + h*HID,
                                                      NN, HID, NN, NN, NH*HID, NH*HID,
                                                      nullptr, nullptr);
    }
    sgemm<false, 0><<<dim3(HID/BN, NN/BM), 256>>>(pHidF, food_W_o, pWhoF,
                                                  NN, HID, NH*HID, NH*HID, HID, HID,
                                                  nullptr, nullptr);
    s1s2_kernel<<<dim3(NN, 1), 256>>>(pWhoF, HID, food_a_o, pS1oF, pS2oF);
    att_build<<<NN, 256>>>(pMaskF, pS1oF, pS2oF, 0, pSimF);
    sgemm<false, 3><<<dim3(HID/BN, NN/BM), 256>>>(pSimF, pWhoF, pEmbF,
                                                  NN, HID, NN, NN, HID, HID,
                                                  nullptr, nullptr);

    // ---- MLP ----
    concat_kernel<<<NN, 512>>>();
    sgemm<false, 2><<<dim3(512/BN, NN/BM), 256>>>(pPair, mlp_W0, pAct0,
                                                  NN, 512, 512, 512, 512, 512,
                                                  nullptr, mlp_b0);
    sgemm<false, 2><<<dim3(256/BN, NN/BM), 256>>>(pAct0, mlp_W1, pAct1,
                                                  NN, 256, 512, 512, 256, 256,
                                                  nullptr, mlp_b1);
    sgemm<false, 2><<<dim3(128/BN, NN/BM), 256>>>(pAct1, mlp_W2, pAct2,
                                                  NN, 128, 256, 256, 128, 128,
                                                  nullptr, mlp_b2);
    mlp_final_kernel<<<NN, 128>>>(pAct2, mlp_W3, mlp_b3, out);
}

// round 6
// speedup vs baseline: 2.1499x; 2.1499x over previous
#include <cuda_runtime.h>
#include <math.h>
#include <float.h>

// ---------------- problem constants ----------------
#define NN   2048
#define DIN  512
#define HID  256
#define NH   4
#define TOPK 6      // k+1
#define MAXD 2048   // no truncation: kNN hubness gives in-degrees in the hundreds

// ---------------- device scratch (static, no allocs) ----------------
__device__ float g_sqU[NN];
__device__ float g_XnF[NN*DIN];
__device__ float g_simU[NN*NN];
__device__ float g_simF[NN*NN];
__device__ int   g_tidxU[NN*TOPK];
__device__ float g_tvalU[NN*TOPK];
__device__ int   g_tidxF[NN*TOPK];
__device__ float g_tvalF[NN*TOPK];
__device__ unsigned char g_maskU[NN*NN];
__device__ unsigned char g_maskF[NN*NN];
__device__ int   g_nbrU[NN*MAXD];
__device__ int   g_cntU[NN];
__device__ int   g_nbrF[NN*MAXD];
__device__ int   g_cntF[NN];
__device__ float g_WcatU[DIN*NH*HID];
__device__ float g_WcatF[DIN*NH*HID];
__device__ float g_WhU[NN*NH*HID];
__device__ float g_WhF[NN*NH*HID];
__device__ float g_s1U[NH*NN];
__device__ float g_s2U[NH*NN];
__device__ float g_s1F[NH*NN];
__device__ float g_s2F[NH*NN];
__device__ float g_hidU[NN*NH*HID];
__device__ float g_hidF[NN*NH*HID];
__device__ float g_WhoU[NN*HID];
__device__ float g_WhoF[NN*HID];
__device__ float g_s1oU[NN];
__device__ float g_s2oU[NN];
__device__ float g_s1oF[NN];
__device__ float g_s2oF[NN];
__device__ float g_embU[NN*HID];
__device__ float g_embF[NN*HID];
__device__ float g_pair[NN*512];
__device__ float g_act0[NN*512];
__device__ float g_act1[NN*256];
__device__ float g_act2[NN*128];

// ---------------- SGEMM: 128x128x16 tile, 256 thr, 8x8 micro, fp32 (PROVEN) ----------------
// TB=false: C[M,Nn] = A[M,K] * B[K,Nn]    (B row-major, leading dim ldb)
// TB=true : C[M,Nn] = A[M,K] * B[Nn,K]^T  (B row-major [Nn,K], leading dim ldb)
// EP: 0 none; 1 negd2 = -((sq[row]+sq[col]) - 2*acc); 2 bias+relu
#define BM 128
#define BN 128
#define BKK 16

template<bool TB, int EP>
__global__ void sgemm(const float* __restrict__ A, const float* __restrict__ B,
                      float* __restrict__ C, int M, int Nn, int Kk,
                      int lda, int ldb, int ldc,
                      const float* __restrict__ sq, const float* __restrict__ bias)
{
    __shared__ float As[BKK][BM+4];
    __shared__ float Bs[BKK][BN+4];
    const int tid = threadIdx.x;
    const int m0 = blockIdx.y * BM;
    const int n0 = blockIdx.x * BN;
    const int tm = (tid / 16) * 8;
    const int tn = (tid % 16) * 8;

    float acc[8][8];
#pragma unroll
    for (int i = 0; i < 8; i++)
#pragma unroll
        for (int j = 0; j < 8; j++) acc[i][j] = 0.f;

    for (int k0 = 0; k0 < Kk; k0 += BKK) {
#pragma unroll
        for (int it = 0; it < 2; it++) {
            int q = tid + it * 256;
            int r = q >> 2;
            int c4 = (q & 3) * 4;
            float4 v = *(const float4*)(A + (size_t)(m0 + r) * lda + k0 + c4);
            As[c4+0][r] = v.x; As[c4+1][r] = v.y; As[c4+2][r] = v.z; As[c4+3][r] = v.w;
        }
        if (!TB) {
#pragma unroll
            for (int it = 0; it < 2; it++) {
                int q = tid + it * 256;
                int r = q >> 5;
                int c4 = (q & 31) * 4;
                float4 v = *(const float4*)(B + (size_t)(k0 + r) * ldb + n0 + c4);
                Bs[r][c4+0] = v.x; Bs[r][c4+1] = v.y; Bs[r][c4+2] = v.z; Bs[r][c4+3] = v.w;
            }
        } else {
#pragma unroll
            for (int it = 0; it < 2; it++) {
                int q = tid + it * 256;
                int r = q >> 2;
                int c4 = (q & 3) * 4;
                float4 v = *(const float4*)(B + (size_t)(n0 + r) * ldb + k0 + c4);
                Bs[c4+0][r] = v.x; Bs[c4+1][r] = v.y; Bs[c4+2][r] = v.z; Bs[c4+3][r] = v.w;
            }
        }
        __syncthreads();

#pragma unroll
        for (int k = 0; k < BKK; k++) {
            float a[8], b[8];
#pragma unroll
            for (int j = 0; j < 8; j++) a[j] = As[k][tm + j];
#pragma unroll
            for (int j = 0; j < 8; j++) b[j] = Bs[k][tn + j];
#pragma unroll
            for (int i = 0; i < 8; i++)
#pragma unroll
                for (int j = 0; j < 8; j++) acc[i][j] = fmaf(a[i], b[j], acc[i][j]);
        }
        __syncthreads();
    }

#pragma unroll
    for (int i = 0; i < 8; i++) {
        int row = m0 + tm + i;
#pragma unroll
        for (int j = 0; j < 8; j++) {
            int col = n0 + tn + j;
            float v = acc[i][j];
            if (EP == 1) v = -((sq[row] + sq[col]) - 2.f * v);
            if (EP == 2) { v += bias[col]; v = fmaxf(v, 0.f); }
            C[(size_t)row * ldc + col] = v;
        }
    }
}

// ---------------- row reductions (PROVEN) ----------------
__global__ void rowsum_sq(const float* __restrict__ X, float* __restrict__ out, int D)
{
    int i = blockIdx.x, tid = threadIdx.x;
    float s = 0.f;
    for (int j = tid; j < D; j += blockDim.x) { float v = X[(size_t)i*D + j]; s = fmaf(v, v, s); }
    __shared__ float r[256];
    r[tid] = s; __syncthreads();
    for (int st = blockDim.x >> 1; st > 0; st >>= 1) { if (tid < st) r[tid] += r[tid + st]; __syncthreads(); }
    if (tid == 0) out[i] = r[0];
}

__global__ void normalize_rows(const float* __restrict__ X, float* __restrict__ Y, int D)
{
    int i = blockIdx.x, tid = threadIdx.x;
    float s = 0.f;
    for (int j = tid; j < D; j += blockDim.x) { float v = X[(size_t)i*D + j]; s = fmaf(v, v, s); }
    __shared__ float r[256];
    r[tid] = s; __syncthreads();
    for (int st = blockDim.x >> 1; st > 0; st >>= 1) { if (tid < st) r[tid] += r[tid + st]; __syncthreads(); }
    float nrm = sqrtf(r[0]);
    for (int j = tid; j < D; j += blockDim.x) Y[(size_t)i*D + j] = X[(size_t)i*D + j] / nrm;
}

// ---------------- brute-force top-6 per row (PROVEN) ----------------
__global__ void top6_bf(const float* __restrict__ S, int* __restrict__ outIdx,
                        float* __restrict__ outVal)
{
    int row = blockIdx.x;
    int lane = threadIdx.x;            // 32 threads
    const float* Sr = S + (size_t)row * NN;
    int chosen[TOPK];
#pragma unroll
    for (int t = 0; t < TOPK; t++) {
        float bv = -FLT_MAX; int bi = 0x7FFFFFFF;
        for (int j = lane; j < NN; j += 32) {
            bool used = false;
#pragma unroll
            for (int u = 0; u < TOPK; u++) if (u < t) used |= (chosen[u] == j);
            if (!used) {
                float x = Sr[j];
                if (x > bv || (x == bv && j < bi)) { bv = x; bi = j; }
            }
        }
        for (int off = 16; off > 0; off >>= 1) {
            float ov = __shfl_down_sync(0xFFFFFFFFu, bv, off);
            int   oi = __shfl_down_sync(0xFFFFFFFFu, bi, off);
            if (ov > bv || (ov == bv && oi < bi)) { bv = ov; bi = oi; }
        }
        bi = __shfl_sync(0xFFFFFFFFu, bi, 0);
        bv = __shfl_sync(0xFFFFFFFFu, bv, 0);
        chosen[t] = bi;
        if (lane == 0) { outIdx[row*TOPK + t] = bi; outVal[row*TOPK + t] = bv; }
    }
}

// ---------------- adjacency mask build (PROVEN) ----------------
__global__ void clear_masks()
{
    int i = blockIdx.x * blockDim.x + threadIdx.x;   // NN*NN/4 words
    ((unsigned int*)g_maskU)[i] = 0u;
    ((unsigned int*)g_maskF)[i] = 0u;
}

__global__ void mark_kernel(const int* __restrict__ idx, const float* __restrict__ val,
                            unsigned char* __restrict__ mask, int needPos)
{
    int i = blockIdx.x * blockDim.x + threadIdx.x;
    if (i >= NN) return;
#pragma unroll
    for (int t = 0; t < TOPK; t++) {
        int j = idx[i*TOPK + t];
        if (j == i) continue;
        if (needPos && !(val[i*TOPK + t] > 0.f)) continue;
        mask[(size_t)i*NN + j] = 1;
        mask[(size_t)j*NN + i] = 1;
    }
}

// ---------------- neighbor list: one THREAD per row, serial ----------------
__global__ void collect_simple(const unsigned char* __restrict__ mask,
                               int* __restrict__ nbr, int* __restrict__ cnt)
{
    int i = blockIdx.x * blockDim.x + threadIdx.x;
    if (i >= NN) return;
    const unsigned char* mr = mask + (size_t)i * NN;
    int c = 0;
    for (int j = 0; j < NN; j++) {
        if (mr[j]) { nbr[(size_t)i*MAXD + c] = j; c++; }
    }
    cnt[i] = c;
}

// ---------------- sparse attention + aggregate + elu (hub-safe, c up to 2048) ----------------
// block = node i, 256 threads (8 warps). nheads=4 (rowStride=1024) or 1 (rowStride=256).
__global__ void att_agg(const float* __restrict__ Wh, int rowStride, int nheads,
                        const float* __restrict__ s1, const float* __restrict__ s2,
                        const int* __restrict__ nbr, const int* __restrict__ cnt,
                        float* __restrict__ out)
{
    __shared__ int   sidx[MAXD];       // 8 KB
    __shared__ float sw[NH][MAXD];     // 32 KB
    __shared__ float hs[NH];
    int i = blockIdx.x, tid = threadIdx.x;
    int wid = tid >> 5, lane = tid & 31;
    int c = cnt[i];

    for (int t = tid; t < c; t += 256) sidx[t] = nbr[(size_t)i*MAXD + t];
    __syncthreads();

    // e-values, parallel over nheads*c
    for (int q = tid; q < nheads*c; q += 256) {
        int h = q / c, t = q - h*c;
        float e = s1[h*NN + i] + s2[h*NN + sidx[t]];
        sw[h][t] = (e >= 0.f) ? e : 0.2f * e;    // leaky relu, alpha=0.2
    }
    __syncthreads();

    // per-head softmax numerator + sum: warp h owns head h
    if (wid < nheads) {
        int h = wid;
        float m = -FLT_MAX;
        for (int t = lane; t < c; t += 32) m = fmaxf(m, sw[h][t]);
#pragma unroll
        for (int o = 16; o > 0; o >>= 1) m = fmaxf(m, __shfl_xor_sync(0xFFFFFFFFu, m, o));
        float s = 0.f;
        for (int t = lane; t < c; t += 32) { float ex = expf(sw[h][t] - m); sw[h][t] = ex; s += ex; }
#pragma unroll
        for (int o = 16; o > 0; o >>= 1) s += __shfl_xor_sync(0xFFFFFFFFu, s, o);
        if (lane == 0) hs[h] = s;
    }
    __syncthreads();

    // normalize
    for (int q = tid; q < nheads*c; q += 256) {
        int h = q / c, t = q - h*c;
        sw[h][t] /= hs[h];
    }
    __syncthreads();

    // gather-aggregate: thread = feature column
    for (int h = 0; h < nheads; h++) {
        float acc = 0.f;
        for (int t = 0; t < c; t++)
            acc = fmaf(sw[h][t], Wh[(size_t)sidx[t]*rowStride + h*HID + tid], acc);
        out[(size_t)i*rowStride + h*HID + tid] = (acc > 0.f) ? acc : expm1f(acc);   // elu
    }
}

// ---------------- GAT helper kernels (PROVEN) ----------------
// W [NH][DIN][HID] -> Wcat [DIN][NH*HID]
__global__ void repack_W(const float* __restrict__ W, float* __restrict__ Wcat)
{
    int i = blockIdx.x * blockDim.x + threadIdx.x;
    if (i >= DIN*NH*HID) return;
    int d = i / (NH*HID);
    int r = i % (NH*HID);
    int h = r / HID;
    int f = r % HID;
    Wcat[i] = W[(size_t)h*DIN*HID + (size_t)d*HID + f];
}

// s1[h*NN+i] = dot(Wh[i, h*256:+256], a[h*512:+256]); s2 second half
__global__ void s1s2_kernel(const float* __restrict__ Wh, int rowStride,
                            const float* __restrict__ a,
                            float* __restrict__ s1, float* __restrict__ s2)
{
    int i = blockIdx.x, h = blockIdx.y, f = threadIdx.x;   // 256 threads
    float w = Wh[(size_t)i*rowStride + h*HID + f];
    float v1 = w * a[h*2*HID + f];
    float v2 = w * a[h*2*HID + HID + f];
    __shared__ float r1[256], r2[256];
    r1[f] = v1; r2[f] = v2; __syncthreads();
    for (int st = 128; st > 0; st >>= 1) {
        if (f < st) { r1[f] += r1[f+st]; r2[f] += r2[f+st]; }
        __syncthreads();
    }
    if (f == 0) { s1[h*NN + i] = r1[0]; s2[h*NN + i] = r2[0]; }
}

// ---------------- MLP pieces (PROVEN) ----------------
__global__ void concat_kernel()
{
    int i = blockIdx.x, c = threadIdx.x;   // 512 threads
    g_pair[(size_t)i*512 + c] = (c < HID) ? g_embU[(size_t)i*HID + c]
                                          : g_embF[(size_t)i*HID + (c - HID)];
}

__global__ void mlp_final_kernel(const float* __restrict__ act, const float* __restrict__ W,
                                 const float* __restrict__ b, float* __restrict__ out)
{
    int i = blockIdx.x, tid = threadIdx.x;   // 128 threads
    float v = act[(size_t)i*128 + tid] * W[tid];
    __shared__ float r[128];
    r[tid] = v; __syncthreads();
    for (int st = 64; st > 0; st >>= 1) { if (tid < st) r[tid] += r[tid+st]; __syncthreads(); }
    if (tid == 0) out[i] = r[0] + b[0];
}

// ---------------- host launch ----------------
template <typename T>
static T* sym(const void* s)
{
    void* p = nullptr;
    cudaGetSymbolAddress(&p, s);
    return (T*)p;
}

extern "C" void kernel_launch(void* const* d_in, const int* in_sizes, int n_in,
                              void* d_out, int out_size)
{
    const float* user_nodes = (const float*)d_in[0];
    const float* food_nodes = (const float*)d_in[1];
    const float* user_W_h   = (const float*)d_in[2];
    const float* user_a_h   = (const float*)d_in[3];
    const float* user_W_o   = (const float*)d_in[4];
    const float* user_a_o   = (const float*)d_in[5];
    const float* food_W_h   = (const float*)d_in[6];
    const float* food_a_h   = (const float*)d_in[7];
    const float* food_W_o   = (const float*)d_in[8];
    const float* food_a_o   = (const float*)d_in[9];
    const float* mlp_W0 = (const float*)d_in[10];
    const float* mlp_b0 = (const float*)d_in[11];
    const float* mlp_W1 = (const float*)d_in[12];
    const float* mlp_b1 = (const float*)d_in[13];
    const float* mlp_W2 = (const float*)d_in[14];
    const float* mlp_b2 = (const float*)d_in[15];
    const float* mlp_W3 = (const float*)d_in[16];
    const float* mlp_b3 = (const float*)d_in[17];
    float* out = (float*)d_out;

    float* pSqU   = sym<float>(g_sqU);
    float* pXnF   = sym<float>(g_XnF);
    float* pSimU  = sym<float>(g_simU);
    float* pSimF  = sym<float>(g_simF);
    int*   pTidxU = sym<int>(g_tidxU);
    float* pTvalU = sym<float>(g_tvalU);
    int*   pTidxF = sym<int>(g_tidxF);
    float* pTvalF = sym<float>(g_tvalF);
    unsigned char* pMaskU = sym<unsigned char>(g_maskU);
    unsigned char* pMaskF = sym<unsigned char>(g_maskF);
    int*   pNbrU = sym<int>(g_nbrU);
    int*   pCntU = sym<int>(g_cntU);
    int*   pNbrF = sym<int>(g_nbrF);
    int*   pCntF = sym<int>(g_cntF);
    float* pWcatU = sym<float>(g_WcatU);
    float* pWcatF = sym<float>(g_WcatF);
    float* pWhU  = sym<float>(g_WhU);
    float* pWhF  = sym<float>(g_WhF);
    float* pS1U  = sym<float>(g_s1U);
    float* pS2U  = sym<float>(g_s2U);
    float* pS1F  = sym<float>(g_s1F);
    float* pS2F  = sym<float>(g_s2F);
    float* pHidU = sym<float>(g_hidU);
    float* pHidF = sym<float>(g_hidF);
    float* pWhoU = sym<float>(g_WhoU);
    float* pWhoF = sym<float>(g_WhoF);
    float* pS1oU = sym<float>(g_s1oU);
    float* pS2oU = sym<float>(g_s2oU);
    float* pS1oF = sym<float>(g_s1oF);
    float* pS2oF = sym<float>(g_s2oF);
    float* pEmbU = sym<float>(g_embU);
    float* pEmbF = sym<float>(g_embF);
    float* pPair = sym<float>(g_pair);
    float* pAct0 = sym<float>(g_act0);
    float* pAct1 = sym<float>(g_act1);
    float* pAct2 = sym<float>(g_act2);

    // ---- graph build ----
    rowsum_sq<<<NN, 256>>>(user_nodes, pSqU, DIN);
    sgemm<true, 1><<<dim3(NN/BN, NN/BM), 256>>>(user_nodes, user_nodes, pSimU,
                                                NN, NN, DIN, DIN, DIN, NN, pSqU, nullptr);
    top6_bf<<<NN, 32>>>(pSimU, pTidxU, pTvalU);

    normalize_rows<<<NN, 256>>>(food_nodes, pXnF, DIN);
    sgemm<true, 0><<<dim3(NN/BN, NN/BM), 256>>>(pXnF, pXnF, pSimF,
                                                NN, NN, DIN, DIN, DIN, NN, nullptr, nullptr);
    top6_bf<<<NN, 32>>>(pSimF, pTidxF, pTvalF);

    clear_masks<<<(NN*NN/4)/256, 256>>>();
    mark_kernel<<<(NN+255)/256, 256>>>(pTidxU, pTvalU, pMaskU, 0);
    mark_kernel<<<(NN+255)/256, 256>>>(pTidxF, pTvalF, pMaskF, 1);
    collect_simple<<<NN/256, 256>>>(pMaskU, pNbrU, pCntU);
    collect_simple<<<NN/256, 256>>>(pMaskF, pNbrF, pCntF);

    // ---- user GAT (sparse attention) ----
    repack_W<<<(DIN*NH*HID + 255)/256, 256>>>(user_W_h, pWcatU);
    sgemm<false, 0><<<dim3((NH*HID)/BN, NN/BM), 256>>>(user_nodes, pWcatU, pWhU,
                                                       NN, NH*HID, DIN, DIN, NH*HID, NH*HID,
                                                       nullptr, nullptr);
    s1s2_kernel<<<dim3(NN, NH), 256>>>(pWhU, NH*HID, user_a_h, pS1U, pS2U);
    att_agg<<<NN, 256>>>(pWhU, NH*HID, NH, pS1U, pS2U, pNbrU, pCntU, pHidU);
    sgemm<false, 0><<<dim3(HID/BN, NN/BM), 256>>>(pHidU, user_W_o, pWhoU,
                                                  NN, HID, NH*HID, NH*HID, HID, HID,
                                                  nullptr, nullptr);
    s1s2_kernel<<<dim3(NN, 1), 256>>>(pWhoU, HID, user_a_o, pS1oU, pS2oU);
    att_agg<<<NN, 256>>>(pWhoU, HID, 1, pS1oU, pS2oU, pNbrU, pCntU, pEmbU);

    // ---- food GAT (sparse attention) ----
    repack_W<<<(DIN*NH*HID + 255)/256, 256>>>(food_W_h, pWcatF);
    sgemm<false, 0><<<dim3((NH*HID)/BN, NN/BM), 256>>>(food_nodes, pWcatF, pWhF,
                                                       NN, NH*HID, DIN, DIN, NH*HID, NH*HID,
                                                       nullptr, nullptr);
    s1s2_kernel<<<dim3(NN, NH), 256>>>(pWhF, NH*HID, food_a_h, pS1F, pS2F);
    att_agg<<<NN, 256>>>(pWhF, NH*HID, NH, pS1F, pS2F, pNbrF, pCntF, pHidF);
    sgemm<false, 0><<<dim3(HID/BN, NN/BM), 256>>>(pHidF, food_W_o, pWhoF,
                                                  NN, HID, NH*HID, NH*HID, HID, HID,
                                                  nullptr, nullptr);
    s1s2_kernel<<<dim3(NN, 1), 256>>>(pWhoF, HID, food_a_o, pS1oF, pS2oF);
    att_agg<<<NN, 256>>>(pWhoF, HID, 1, pS1oF, pS2oF, pNbrF, pCntF, pEmbF);

    // ---- MLP ----
    concat_kernel<<<NN, 512>>>();
    sgemm<false, 2><<<dim3(512/BN, NN/BM), 256>>>(pPair, mlp_W0, pAct0,
                                                  NN, 512, 512, 512, 512, 512,
                                                  nullptr, mlp_b0);
    sgemm<false, 2><<<dim3(256/BN, NN/BM), 256>>>(pAct0, mlp_W1, pAct1,
                                                  NN, 256, 512, 512, 256, 256,
                                                  nullptr, mlp_b1);
    sgemm<false, 2><<<dim3(128/BN, NN/BM), 256>>>(pAct1, mlp_W2, pAct2,
                                                  NN, 128, 256, 256, 128, 128,
                                                  nullptr, mlp_b2);
    mlp_final_kernel<<<NN, 128>>>(pAct2, mlp_W3, mlp_b3, out);
}

// round 7
// speedup vs baseline: 5.2658x; 2.4493x over previous
#include <cuda_runtime.h>
#include <math.h>
#include <float.h>

// ---------------- problem constants ----------------
#define NN   2048
#define DIN  512
#define HID  256
#define NH   4
#define TOPK 6      // k+1
#define MAXD 2048   // no truncation (kNN hubness gives in-degrees in the hundreds)
#define BKK  16

// ---------------- device scratch (static, no allocs) ----------------
__device__ float g_sqU[NN];
__device__ float g_XnF[NN*DIN];
__device__ float g_simU[NN*NN];
__device__ float g_simF[NN*NN];
__device__ int   g_tidxU[NN*TOPK];
__device__ float g_tvalU[NN*TOPK];
__device__ int   g_tidxF[NN*TOPK];
__device__ float g_tvalF[NN*TOPK];
__device__ unsigned char g_maskU[NN*NN];
__device__ unsigned char g_maskF[NN*NN];
__device__ int   g_nbrU[NN*MAXD];
__device__ int   g_cntU[NN];
__device__ int   g_nbrF[NN*MAXD];
__device__ int   g_cntF[NN];
__device__ float g_WcatU[DIN*NH*HID];
__device__ float g_WcatF[DIN*NH*HID];
__device__ float g_WhU[NN*NH*HID];
__device__ float g_WhF[NN*NH*HID];
__device__ float g_s1U[NH*NN];
__device__ float g_s2U[NH*NN];
__device__ float g_s1F[NH*NN];
__device__ float g_s2F[NH*NN];
__device__ float g_hidU[NN*NH*HID];
__device__ float g_hidF[NN*NH*HID];
__device__ float g_WhoU[NN*HID];
__device__ float g_WhoF[NN*HID];
__device__ float g_s1oU[NN];
__device__ float g_s2oU[NN];
__device__ float g_s1oF[NN];
__device__ float g_s2oF[NN];
__device__ float g_embU[NN*HID];
__device__ float g_embF[NN*HID];
__device__ float g_pair[NN*512];
__device__ float g_act0[NN*512];
__device__ float g_act1[NN*256];
__device__ float g_act2[NN*128];

// ---------------- SGEMM: double-buffered, templated tile, fp32 ----------------
// TB=false: C[M,Nn] = A[M,K] * B[K,Nn]    (B row-major, leading dim ldb)
// TB=true : C[M,Nn] = A[M,K] * B[Nn,K]^T  (B row-major [Nn,K], leading dim ldb)
// EP: 0 none; 1 negd2 = -((sq[row]+sq[col]) - 2*acc); 2 bias+relu
// SYM: grid.x enumerates upper-tri tile pairs; writes tile and its mirror.
// Per-output-element accumulation order is identical to the proven R6 kernel
// (same k ordering, fmaf chain) -> bitwise identical results.
template<bool TB, int EP, bool SYM, int TBM, int TBN, int TMI, int TNI>
__launch_bounds__(256, 2)
__global__ void sgemm(const float* __restrict__ A, const float* __restrict__ B,
                      float* __restrict__ C, int M, int Nn, int Kk,
                      int lda, int ldb, int ldc,
                      const float* __restrict__ sq, const float* __restrict__ bias)
{
    static_assert((TBM/TMI)*(TBN/TNI) == 256, "thread count");
    __shared__ float As[2][BKK][TBM+4];
    __shared__ float Bs[2][BKK][TBN+4];
    const int tid = threadIdx.x;
    int bx = blockIdx.x, by = blockIdx.y;
    if (SYM) {
        int nb = M / TBM;
        int idx = blockIdx.x, bi = 0;
        while (idx >= nb - bi) { idx -= nb - bi; bi++; }
        by = bi; bx = bi + idx;
    }
    const int m0 = by * TBM, n0 = bx * TBN;
    const int tm = (tid / (TBN/TNI)) * TMI;
    const int tn = (tid % (TBN/TNI)) * TNI;

    const int AIT = TBM*BKK/4/256 > 0 ? TBM*BKK/4/256 : 1;
    const int BIT = TBN*BKK/4/256 > 0 ? TBN*BKK/4/256 : 1;
    float4 ra[AIT], rb[BIT];

    auto LOADA = [&](int k0) {
#pragma unroll
        for (int it = 0; it < AIT; it++) {
            int q = tid + it*256;
            int r = q >> 2, c4 = (q & 3) * 4;
            ra[it] = *(const float4*)(A + (size_t)(m0 + r)*lda + k0 + c4);
        }
    };
    auto STOREA = [&](int buf) {
#pragma unroll
        for (int it = 0; it < AIT; it++) {
            int q = tid + it*256;
            int r = q >> 2, c4 = (q & 3) * 4;
            As[buf][c4+0][r] = ra[it].x; As[buf][c4+1][r] = ra[it].y;
            As[buf][c4+2][r] = ra[it].z; As[buf][c4+3][r] = ra[it].w;
        }
    };
    auto LOADB = [&](int k0) {
#pragma unroll
        for (int it = 0; it < BIT; it++) {
            int q = tid + it*256;
            if (!TB) {
                int r = q / (TBN/4), cn = (q % (TBN/4)) * 4;
                rb[it] = *(const float4*)(B + (size_t)(k0 + r)*ldb + n0 + cn);
            } else {
                int r = q >> 2, c4 = (q & 3) * 4;
                rb[it] = *(const float4*)(B + (size_t)(n0 + r)*ldb + k0 + c4);
            }
        }
    };
    auto STOREB = [&](int buf) {
#pragma unroll
        for (int it = 0; it < BIT; it++) {
            int q = tid + it*256;
            if (!TB) {
                int r = q / (TBN/4), cn = (q % (TBN/4)) * 4;
                Bs[buf][r][cn+0] = rb[it].x; Bs[buf][r][cn+1] = rb[it].y;
                Bs[buf][r][cn+2] = rb[it].z; Bs[buf][r][cn+3] = rb[it].w;
            } else {
                int r = q >> 2, c4 = (q & 3) * 4;
                Bs[buf][c4+0][r] = rb[it].x; Bs[buf][c4+1][r] = rb[it].y;
                Bs[buf][c4+2][r] = rb[it].z; Bs[buf][c4+3][r] = rb[it].w;
            }
        }
    };

    float acc[TMI][TNI];
#pragma unroll
    for (int i = 0; i < TMI; i++)
#pragma unroll
        for (int j = 0; j < TNI; j++) acc[i][j] = 0.f;

    auto COMPUTE = [&](int buf) {
#pragma unroll
        for (int k = 0; k < BKK; k++) {
            float a[TMI], b[TNI];
#pragma unroll
            for (int u = 0; u < TMI/4; u++) {
                float4 v = *(const float4*)&As[buf][k][tm + u*4];
                a[u*4+0] = v.x; a[u*4+1] = v.y; a[u*4+2] = v.z; a[u*4+3] = v.w;
            }
#pragma unroll
            for (int u = 0; u < TNI/4; u++) {
                float4 v = *(const float4*)&Bs[buf][k][tn + u*4];
                b[u*4+0] = v.x; b[u*4+1] = v.y; b[u*4+2] = v.z; b[u*4+3] = v.w;
            }
#pragma unroll
            for (int i = 0; i < TMI; i++)
#pragma unroll
                for (int j = 0; j < TNI; j++) acc[i][j] = fmaf(a[i], b[j], acc[i][j]);
        }
    };

    LOADA(0); LOADB(0);
    STOREA(0); STOREB(0);
    __syncthreads();
    int buf = 0;
    for (int k0 = BKK; k0 < Kk; k0 += BKK) {
        LOADA(k0); LOADB(k0);       // global prefetch overlapped with compute
        COMPUTE(buf);
        STOREA(buf ^ 1); STOREB(buf ^ 1);
        __syncthreads();
        buf ^= 1;
    }
    COMPUTE(buf);

#pragma unroll
    for (int i = 0; i < TMI; i++) {
        int row = m0 + tm + i;
#pragma unroll
        for (int j = 0; j < TNI; j++) {
            int col = n0 + tn + j;
            float v = acc[i][j];
            if (EP == 1) v = -((sq[row] + sq[col]) - 2.f * v);
            if (EP == 2) { v += bias[col]; v = fmaxf(v, 0.f); }
            C[(size_t)row * ldc + col] = v;
            if (SYM && bx != by) C[(size_t)col * ldc + row] = v;
        }
    }
}

// ---------------- row reductions (PROVEN) ----------------
__global__ void rowsum_sq(const float* __restrict__ X, float* __restrict__ out, int D)
{
    int i = blockIdx.x, tid = threadIdx.x;
    float s = 0.f;
    for (int j = tid; j < D; j += blockDim.x) { float v = X[(size_t)i*D + j]; s = fmaf(v, v, s); }
    __shared__ float r[256];
    r[tid] = s; __syncthreads();
    for (int st = blockDim.x >> 1; st > 0; st >>= 1) { if (tid < st) r[tid] += r[tid + st]; __syncthreads(); }
    if (tid == 0) out[i] = r[0];
}

__global__ void normalize_rows(const float* __restrict__ X, float* __restrict__ Y, int D)
{
    int i = blockIdx.x, tid = threadIdx.x;
    float s = 0.f;
    for (int j = tid; j < D; j += blockDim.x) { float v = X[(size_t)i*D + j]; s = fmaf(v, v, s); }
    __shared__ float r[256];
    r[tid] = s; __syncthreads();
    for (int st = blockDim.x >> 1; st > 0; st >>= 1) { if (tid < st) r[tid] += r[tid + st]; __syncthreads(); }
    float nrm = sqrtf(r[0]);
    for (int j = tid; j < D; j += blockDim.x) Y[(size_t)i*D + j] = X[(size_t)i*D + j] / nrm;
}

// ---------------- top-6 per row: 128 threads, 6 argmax passes ----------------
// Same deterministic selection (value desc, index-asc tiebreak) as proven version.
__global__ void top6_bf(const float* __restrict__ S, int* __restrict__ outIdx,
                        float* __restrict__ outVal)
{
    __shared__ float sv[128];
    __shared__ int   si[128];
    __shared__ int   ch[TOPK];
    int row = blockIdx.x, tid = threadIdx.x;
    const float* Sr = S + (size_t)row * NN;
    for (int t = 0; t < TOPK; t++) {
        int cc[TOPK];
#pragma unroll
        for (int u = 0; u < TOPK; u++) cc[u] = (u < t) ? ch[u] : -1;
        float bv = -FLT_MAX; int bi = 0x7FFFFFFF;
        for (int j = tid; j < NN; j += 128) {
            bool used = false;
#pragma unroll
            for (int u = 0; u < TOPK; u++) used |= (cc[u] == j);
            if (!used) {
                float x = Sr[j];
                if (x > bv || (x == bv && j < bi)) { bv = x; bi = j; }
            }
        }
        sv[tid] = bv; si[tid] = bi;
        __syncthreads();
        if (tid < 32) {
#pragma unroll
            for (int o = 32; o < 128; o += 32) {
                float ov = sv[tid + o]; int oi = si[tid + o];
                if (ov > bv || (ov == bv && oi < bi)) { bv = ov; bi = oi; }
            }
#pragma unroll
            for (int o = 16; o > 0; o >>= 1) {
                float ov = __shfl_down_sync(0xFFFFFFFFu, bv, o);
                int   oi = __shfl_down_sync(0xFFFFFFFFu, bi, o);
                if (ov > bv || (ov == bv && oi < bi)) { bv = ov; bi = oi; }
            }
            if (tid == 0) {
                ch[t] = bi;
                outIdx[row*TOPK + t] = bi;
                outVal[row*TOPK + t] = bv;
            }
        }
        __syncthreads();
    }
}

// ---------------- adjacency mask build (PROVEN) ----------------
__global__ void clear_masks()
{
    int i = blockIdx.x * blockDim.x + threadIdx.x;   // NN*NN/4 words
    ((unsigned int*)g_maskU)[i] = 0u;
    ((unsigned int*)g_maskF)[i] = 0u;
}

__global__ void mark_kernel(const int* __restrict__ idx, const float* __restrict__ val,
                            unsigned char* __restrict__ mask, int needPos)
{
    int i = blockIdx.x * blockDim.x + threadIdx.x;
    if (i >= NN) return;
#pragma unroll
    for (int t = 0; t < TOPK; t++) {
        int j = idx[i*TOPK + t];
        if (j == i) continue;
        if (needPos && !(val[i*TOPK + t] > 0.f)) continue;
        mask[(size_t)i*NN + j] = 1;
        mask[(size_t)j*NN + i] = 1;
    }
}

// ---------------- neighbor list: warp-ballot compaction (ascending order) ----------------
__global__ void collect_kernel(const unsigned char* __restrict__ mask,
                               int* __restrict__ nbr, int* __restrict__ cnt)
{
    int warp = (blockIdx.x * blockDim.x + threadIdx.x) >> 5;
    int lane = threadIdx.x & 31;
    if (warp >= NN) return;
    const unsigned char* mr = mask + (size_t)warp * NN;
    int c = 0;
    for (int base = 0; base < NN; base += 32) {
        bool m = mr[base + lane] != 0;
        unsigned b = __ballot_sync(0xFFFFFFFFu, m);
        if (m) nbr[(size_t)warp*MAXD + c + __popc(b & ((1u << lane) - 1u))] = base + lane;
        c += __popc(b);
    }
    if (lane == 0) cnt[warp] = c;
}

// ---------------- sparse attention + aggregate + elu (hub-safe, PROVEN R6) ----------------
__global__ void att_agg(const float* __restrict__ Wh, int rowStride, int nheads,
                        const float* __restrict__ s1, const float* __restrict__ s2,
                        const int* __restrict__ nbr, const int* __restrict__ cnt,
                        float* __restrict__ out)
{
    __shared__ int   sidx[MAXD];       // 8 KB
    __shared__ float sw[NH][MAXD];     // 32 KB
    __shared__ float hs[NH];
    int i = blockIdx.x, tid = threadIdx.x;
    int wid = tid >> 5, lane = tid & 31;
    int c = cnt[i];

    for (int t = tid; t < c; t += 256) sidx[t] = nbr[(size_t)i*MAXD + t];
    __syncthreads();

    for (int q = tid; q < nheads*c; q += 256) {
        int h = q / c, t = q - h*c;
        float e = s1[h*NN + i] + s2[h*NN + sidx[t]];
        sw[h][t] = (e >= 0.f) ? e : 0.2f * e;
    }
    __syncthreads();

    if (wid < nheads) {
        int h = wid;
        float m = -FLT_MAX;
        for (int t = lane; t < c; t += 32) m = fmaxf(m, sw[h][t]);
#pragma unroll
        for (int o = 16; o > 0; o >>= 1) m = fmaxf(m, __shfl_xor_sync(0xFFFFFFFFu, m, o));
        float s = 0.f;
        for (int t = lane; t < c; t += 32) { float ex = expf(sw[h][t] - m); sw[h][t] = ex; s += ex; }
#pragma unroll
        for (int o = 16; o > 0; o >>= 1) s += __shfl_xor_sync(0xFFFFFFFFu, s, o);
        if (lane == 0) hs[h] = s;
    }
    __syncthreads();

    for (int q = tid; q < nheads*c; q += 256) {
        int h = q / c, t = q - h*c;
        sw[h][t] /= hs[h];
    }
    __syncthreads();

    for (int h = 0; h < nheads; h++) {
        float acc = 0.f;
#pragma unroll 4
        for (int t = 0; t < c; t++)
            acc = fmaf(sw[h][t], Wh[(size_t)sidx[t]*rowStride + h*HID + tid], acc);
        out[(size_t)i*rowStride + h*HID + tid] = (acc > 0.f) ? acc : expm1f(acc);
    }
}

// ---------------- GAT helper kernels (PROVEN) ----------------
__global__ void repack_W(const float* __restrict__ W, float* __restrict__ Wcat)
{
    int i = blockIdx.x * blockDim.x + threadIdx.x;
    if (i >= DIN*NH*HID) return;
    int d = i / (NH*HID);
    int r = i % (NH*HID);
    int h = r / HID;
    int f = r % HID;
    Wcat[i] = W[(size_t)h*DIN*HID + (size_t)d*HID + f];
}

__global__ void s1s2_kernel(const float* __restrict__ Wh, int rowStride,
                            const float* __restrict__ a,
                            float* __restrict__ s1, float* __restrict__ s2)
{
    int i = blockIdx.x, h = blockIdx.y, f = threadIdx.x;   // 256 threads
    float w = Wh[(size_t)i*rowStride + h*HID + f];
    float v1 = w * a[h*2*HID + f];
    float v2 = w * a[h*2*HID + HID + f];
    __shared__ float r1[256], r2[256];
    r1[f] = v1; r2[f] = v2; __syncthreads();
    for (int st = 128; st > 0; st >>= 1) {
        if (f < st) { r1[f] += r1[f+st]; r2[f] += r2[f+st]; }
        __syncthreads();
    }
    if (f == 0) { s1[h*NN + i] = r1[0]; s2[h*NN + i] = r2[0]; }
}

// ---------------- MLP pieces (PROVEN) ----------------
__global__ void concat_kernel()
{
    int i = blockIdx.x, c = threadIdx.x;   // 512 threads
    g_pair[(size_t)i*512 + c] = (c < HID) ? g_embU[(size_t)i*HID + c]
                                          : g_embF[(size_t)i*HID + (c - HID)];
}

__global__ void mlp_final_kernel(const float* __restrict__ act, const float* __restrict__ W,
                                 const float* __restrict__ b, float* __restrict__ out)
{
    int i = blockIdx.x, tid = threadIdx.x;   // 128 threads
    float v = act[(size_t)i*128 + tid] * W[tid];
    __shared__ float r[128];
    r[tid] = v; __syncthreads();
    for (int st = 64; st > 0; st >>= 1) { if (tid < st) r[tid] += r[tid+st]; __syncthreads(); }
    if (tid == 0) out[i] = r[0] + b[0];
}

// ---------------- host launch ----------------
template <typename T>
static T* sym(const void* s)
{
    void* p = nullptr;
    cudaGetSymbolAddress(&p, s);
    return (T*)p;
}

extern "C" void kernel_launch(void* const* d_in, const int* in_sizes, int n_in,
                              void* d_out, int out_size)
{
    const float* user_nodes = (const float*)d_in[0];
    const float* food_nodes = (const float*)d_in[1];
    const float* user_W_h   = (const float*)d_in[2];
    const float* user_a_h   = (const float*)d_in[3];
    const float* user_W_o   = (const float*)d_in[4];
    const float* user_a_o   = (const float*)d_in[5];
    const float* food_W_h   = (const float*)d_in[6];
    const float* food_a_h   = (const float*)d_in[7];
    const float* food_W_o   = (const float*)d_in[8];
    const float* food_a_o   = (const float*)d_in[9];
    const float* mlp_W0 = (const float*)d_in[10];
    const float* mlp_b0 = (const float*)d_in[11];
    const float* mlp_W1 = (const float*)d_in[12];
    const float* mlp_b1 = (const float*)d_in[13];
    const float* mlp_W2 = (const float*)d_in[14];
    const float* mlp_b2 = (const float*)d_in[15];
    const float* mlp_W3 = (const float*)d_in[16];
    const float* mlp_b3 = (const float*)d_in[17];
    float* out = (float*)d_out;

    float* pSqU   = sym<float>(g_sqU);
    float* pXnF   = sym<float>(g_XnF);
    float* pSimU  = sym<float>(g_simU);
    float* pSimF  = sym<float>(g_simF);
    int*   pTidxU = sym<int>(g_tidxU);
    float* pTvalU = sym<float>(g_tvalU);
    int*   pTidxF = sym<int>(g_tidxF);
    float* pTvalF = sym<float>(g_tvalF);
    unsigned char* pMaskU = sym<unsigned char>(g_maskU);
    unsigned char* pMaskF = sym<unsigned char>(g_maskF);
    int*   pNbrU = sym<int>(g_nbrU);
    int*   pCntU = sym<int>(g_cntU);
    int*   pNbrF = sym<int>(g_nbrF);
    int*   pCntF = sym<int>(g_cntF);
    float* pWcatU = sym<float>(g_WcatU);
    float* pWcatF = sym<float>(g_WcatF);
    float* pWhU  = sym<float>(g_WhU);
    float* pWhF  = sym<float>(g_WhF);
    float* pS1U  = sym<float>(g_s1U);
    float* pS2U  = sym<float>(g_s2U);
    float* pS1F  = sym<float>(g_s1F);
    float* pS2F  = sym<float>(g_s2F);
    float* pHidU = sym<float>(g_hidU);
    float* pHidF = sym<float>(g_hidF);
    float* pWhoU = sym<float>(g_WhoU);
    float* pWhoF = sym<float>(g_WhoF);
    float* pS1oU = sym<float>(g_s1oU);
    float* pS2oU = sym<float>(g_s2oU);
    float* pS1oF = sym<float>(g_s1oF);
    float* pS2oF = sym<float>(g_s2oF);
    float* pEmbU = sym<float>(g_embU);
    float* pEmbF = sym<float>(g_embF);
    float* pPair = sym<float>(g_pair);
    float* pAct0 = sym<float>(g_act0);
    float* pAct1 = sym<float>(g_act1);
    float* pAct2 = sym<float>(g_act2);

    const int NTRI = (NN/128) * (NN/128 + 1) / 2;   // 136 upper-tri tiles

    // ---- graph build ----
    rowsum_sq<<<NN, 256>>>(user_nodes, pSqU, DIN);
    sgemm<true, 1, true, 128,128,8,8><<<NTRI, 256>>>(user_nodes, user_nodes, pSimU,
                                                     NN, NN, DIN, DIN, DIN, NN, pSqU, nullptr);
    top6_bf<<<NN, 128>>>(pSimU, pTidxU, pTvalU);

    normalize_rows<<<NN, 256>>>(food_nodes, pXnF, DIN);
    sgemm<true, 0, true, 128,128,8,8><<<NTRI, 256>>>(pXnF, pXnF, pSimF,
                                                     NN, NN, DIN, DIN, DIN, NN, nullptr, nullptr);
    top6_bf<<<NN, 128>>>(pSimF, pTidxF, pTvalF);

    clear_masks<<<(NN*NN/4)/256, 256>>>();
    mark_kernel<<<(NN+255)/256, 256>>>(pTidxU, pTvalU, pMaskU, 0);
    mark_kernel<<<(NN+255)/256, 256>>>(pTidxF, pTvalF, pMaskF, 1);
    collect_kernel<<<NN*32/256, 256>>>(pMaskU, pNbrU, pCntU);
    collect_kernel<<<NN*32/256, 256>>>(pMaskF, pNbrF, pCntF);

    // ---- user GAT ----
    repack_W<<<(DIN*NH*HID + 255)/256, 256>>>(user_W_h, pWcatU);
    sgemm<false, 0, false, 128,128,8,8><<<dim3((NH*HID)/128, NN/128), 256>>>(
        user_nodes, pWcatU, pWhU, NN, NH*HID, DIN, DIN, NH*HID, NH*HID, nullptr, nullptr);
    s1s2_kernel<<<dim3(NN, NH), 256>>>(pWhU, NH*HID, user_a_h, pS1U, pS2U);
    att_agg<<<NN, 256>>>(pWhU, NH*HID, NH, pS1U, pS2U, pNbrU, pCntU, pHidU);
    sgemm<false, 0, false, 64,64,4,4><<<dim3(HID/64, NN/64), 256>>>(
        pHidU, user_W_o, pWhoU, NN, HID, NH*HID, NH*HID, HID, HID, nullptr, nullptr);
    s1s2_kernel<<<dim3(NN, 1), 256>>>(pWhoU, HID, user_a_o, pS1oU, pS2oU);
    att_agg<<<NN, 256>>>(pWhoU, HID, 1, pS1oU, pS2oU, pNbrU, pCntU, pEmbU);

    // ---- food GAT ----
    repack_W<<<(DIN*NH*HID + 255)/256, 256>>>(food_W_h, pWcatF);
    sgemm<false, 0, false, 128,128,8,8><<<dim3((NH*HID)/128, NN/128), 256>>>(
        food_nodes, pWcatF, pWhF, NN, NH*HID, DIN, DIN, NH*HID, NH*HID, nullptr, nullptr);
    s1s2_kernel<<<dim3(NN, NH), 256>>>(pWhF, NH*HID, food_a_h, pS1F, pS2F);
    att_agg<<<NN, 256>>>(pWhF, NH*HID, NH, pS1F, pS2F, pNbrF, pCntF, pHidF);
    sgemm<false, 0, false, 64,64,4,4><<<dim3(HID/64, NN/64), 256>>>(
        pHidF, food_W_o, pWhoF, NN, HID, NH*HID, NH*HID, HID, HID, nullptr, nullptr);
    s1s2_kernel<<<dim3(NN, 1), 256>>>(pWhoF, HID, food_a_o, pS1oF, pS2oF);
    att_agg<<<NN, 256>>>(pWhoF, HID, 1, pS1oF, pS2oF, pNbrF, pCntF, pEmbF);

    // ---- MLP ----
    concat_kernel<<<NN, 512>>>();
    sgemm<false, 2, false, 64,64,4,4><<<dim3(512/64, NN/64), 256>>>(
        pPair, mlp_W0, pAct0, NN, 512, 512, 512, 512, 512, nullptr, mlp_b0);
    sgemm<false, 2, false, 64,64,4,4><<<dim3(256/64, NN/64), 256>>>(
        pAct0, mlp_W1, pAct1, NN, 256, 512, 512, 256, 256, nullptr, mlp_b1);
    sgemm<false, 2, false, 64,64,4,4><<<dim3(128/64, NN/64), 256>>>(
        pAct1, mlp_W2, pAct2, NN, 128, 256, 256, 128, 128, nullptr, mlp_b2);
    mlp_final_kernel<<<NN, 128>>>(pAct2, mlp_W3, mlp_b3, out);
}

// round 9
// speedup vs baseline: 6.1603x; 1.1699x over previous
#include <cuda_runtime.h>
#include <math.h>
#include <float.h>

// ---------------- problem constants ----------------
#define NN   2048
#define DIN  512
#define HID  256
#define NH   4
#define TOPK 6      // k+1
#define MAXD 2048   // no truncation (kNN hubness gives in-degrees in the hundreds)
#define BKK  16

// ---------------- device scratch (static, no allocs; zero-initialized) ----------------
__device__ float g_zero[NN];       // stays all-zero
__device__ float g_sqU[NN];
__device__ float g_XnF[NN*DIN];
__device__ float g_simU[NN*NN];
__device__ float g_simF[NN*NN];
__device__ int   g_tidxU[NN*TOPK];
__device__ float g_tvalU[NN*TOPK];
__device__ int   g_tidxF[NN*TOPK];
__device__ float g_tvalF[NN*TOPK];
__device__ unsigned char g_maskU[NN*NN];
__device__ unsigned char g_maskF[NN*NN];
__device__ int   g_nbrU[NN*MAXD];
__device__ int   g_cntU[NN];
__device__ int   g_nbrF[NN*MAXD];
__device__ int   g_cntF[NN];
__device__ float g_WcatU[DIN*NH*HID];
__device__ float g_WcatF[DIN*NH*HID];
__device__ float g_WhU[NN*NH*HID];
__device__ float g_WhF[NN*NH*HID];
__device__ float g_s1U[NH*NN];
__device__ float g_s2U[NH*NN];
__device__ float g_s1F[NH*NN];
__device__ float g_s2F[NH*NN];
__device__ float g_hidU[NN*NH*HID];
__device__ float g_hidF[NN*NH*HID];
__device__ float g_WhoU[NN*HID];
__device__ float g_WhoF[NN*HID];
__device__ float g_s1oU[NN];
__device__ float g_s2oU[NN];
__device__ float g_s1oF[NN];
__device__ float g_s2oF[NN];
__device__ float g_embU[NN*HID];
__device__ float g_embF[NN*HID];
__device__ float g_pair[NN*512];
__device__ float g_act0[NN*512];
__device__ float g_act1[NN*256];
__device__ float g_act2[NN*128];

// ---------------- SGEMM: double-buffered, templated tile, z-batched (x2), fp32 ----------------
// TB=false: C[M,Nn] = A[M,K]*B[K,Nn]; TB=true: C = A[M,K]*B[Nn,K]^T
// EP: 0 none; 1 negd2 = -((sq[row]+sq[col]) - 2*acc); 2 bias+relu
// SYM: grid.x enumerates upper-tri tile pairs; writes tile and mirror.
// blockIdx.z in {0,1} picks the (A,B,C,sq,bias) set. Accumulation order identical
// to the proven R6/R7 kernel -> bitwise identical results.
template<bool TB, int EP, bool SYM, int TBM, int TBN, int TMI, int TNI>
__launch_bounds__(256, 2)
__global__ void sgemm2(const float* __restrict__ A0, const float* __restrict__ B0,
                       float* __restrict__ C0, const float* __restrict__ sq0,
                       const float* __restrict__ bias0,
                       const float* __restrict__ A1, const float* __restrict__ B1,
                       float* __restrict__ C1, const float* __restrict__ sq1,
                       const float* __restrict__ bias1,
                       int M, int Nn, int Kk, int lda, int ldb, int ldc)
{
    static_assert((TBM/TMI)*(TBN/TNI) == 256, "thread count");
    const float* A    = blockIdx.z ? A1 : A0;
    const float* B    = blockIdx.z ? B1 : B0;
    float*       C    = blockIdx.z ? C1 : C0;
    const float* sq   = blockIdx.z ? sq1 : sq0;
    const float* bias = blockIdx.z ? bias1 : bias0;

    __shared__ float As[2][BKK][TBM+4];
    __shared__ float Bs[2][BKK][TBN+4];
    const int tid = threadIdx.x;
    int bx = blockIdx.x, by = blockIdx.y;
    if (SYM) {
        int nb = M / TBM;
        int idx = blockIdx.x, bi = 0;
        while (idx >= nb - bi) { idx -= nb - bi; bi++; }
        by = bi; bx = bi + idx;
    }
    const int m0 = by * TBM, n0 = bx * TBN;
    const int tm = (tid / (TBN/TNI)) * TMI;
    const int tn = (tid % (TBN/TNI)) * TNI;

    const int AIT = TBM*BKK/4/256 > 0 ? TBM*BKK/4/256 : 1;
    const int BIT = TBN*BKK/4/256 > 0 ? TBN*BKK/4/256 : 1;
    float4 ra[AIT], rb[BIT];

    auto LOADA = [&](int k0) {
#pragma unroll
        for (int it = 0; it < AIT; it++) {
            int q = tid + it*256;
            int r = q >> 2, c4 = (q & 3) * 4;
            ra[it] = *(const float4*)(A + (size_t)(m0 + r)*lda + k0 + c4);
        }
    };
    auto STOREA = [&](int buf) {
#pragma unroll
        for (int it = 0; it < AIT; it++) {
            int q = tid + it*256;
            int r = q >> 2, c4 = (q & 3) * 4;
            As[buf][c4+0][r] = ra[it].x; As[buf][c4+1][r] = ra[it].y;
            As[buf][c4+2][r] = ra[it].z; As[buf][c4+3][r] = ra[it].w;
        }
    };
    auto LOADB = [&](int k0) {
#pragma unroll
        for (int it = 0; it < BIT; it++) {
            int q = tid + it*256;
            if (!TB) {
                int r = q / (TBN/4), cn = (q % (TBN/4)) * 4;
                rb[it] = *(const float4*)(B + (size_t)(k0 + r)*ldb + n0 + cn);
            } else {
                int r = q >> 2, c4 = (q & 3) * 4;
                rb[it] = *(const float4*)(B + (size_t)(n0 + r)*ldb + k0 + c4);
            }
        }
    };
    auto STOREB = [&](int buf) {
#pragma unroll
        for (int it = 0; it < BIT; it++) {
            int q = tid + it*256;
            if (!TB) {
                int r = q / (TBN/4), cn = (q % (TBN/4)) * 4;
                Bs[buf][r][cn+0] = rb[it].x; Bs[buf][r][cn+1] = rb[it].y;
                Bs[buf][r][cn+2] = rb[it].z; Bs[buf][r][cn+3] = rb[it].w;
            } else {
                int r = q >> 2, c4 = (q & 3) * 4;
                Bs[buf][c4+0][r] = rb[it].x; Bs[buf][c4+1][r] = rb[it].y;
                Bs[buf][c4+2][r] = rb[it].z; Bs[buf][c4+3][r] = rb[it].w;
            }
        }
    };

    float acc[TMI][TNI];
#pragma unroll
    for (int i = 0; i < TMI; i++)
#pragma unroll
        for (int j = 0; j < TNI; j++) acc[i][j] = 0.f;

    auto COMPUTE = [&](int buf) {
#pragma unroll
        for (int k = 0; k < BKK; k++) {
            float a[TMI], b[TNI];
#pragma unroll
            for (int u = 0; u < TMI/4; u++) {
                float4 v = *(const float4*)&As[buf][k][tm + u*4];
                a[u*4+0] = v.x; a[u*4+1] = v.y; a[u*4+2] = v.z; a[u*4+3] = v.w;
            }
#pragma unroll
            for (int u = 0; u < TNI/4; u++) {
                float4 v = *(const float4*)&Bs[buf][k][tn + u*4];
                b[u*4+0] = v.x; b[u*4+1] = v.y; b[u*4+2] = v.z; b[u*4+3] = v.w;
            }
#pragma unroll
            for (int i = 0; i < TMI; i++)
#pragma unroll
                for (int j = 0; j < TNI; j++) acc[i][j] = fmaf(a[i], b[j], acc[i][j]);
        }
    };

    LOADA(0); LOADB(0);
    STOREA(0); STOREB(0);
    __syncthreads();
    int buf = 0;
    for (int k0 = BKK; k0 < Kk; k0 += BKK) {
        LOADA(k0); LOADB(k0);
        COMPUTE(buf);
        STOREA(buf ^ 1); STOREB(buf ^ 1);
        __syncthreads();
        buf ^= 1;
    }
    COMPUTE(buf);

#pragma unroll
    for (int i = 0; i < TMI; i++) {
        int row = m0 + tm + i;
#pragma unroll
        for (int j = 0; j < TNI; j++) {
            int col = n0 + tn + j;
            float v = acc[i][j];
            if (EP == 1) v = -((sq[row] + sq[col]) - 2.f * v);
            if (EP == 2) { v += bias[col]; v = fmaxf(v, 0.f); }
            C[(size_t)row * ldc + col] = v;
            if (SYM && bx != by) C[(size_t)col * ldc + row] = v;
        }
    }
}

// ---------------- row reductions (PROVEN) ----------------
__global__ void rowsum_sq(const float* __restrict__ X, float* __restrict__ out, int D)
{
    int i = blockIdx.x, tid = threadIdx.x;
    float s = 0.f;
    for (int j = tid; j < D; j += blockDim.x) { float v = X[(size_t)i*D + j]; s = fmaf(v, v, s); }
    __shared__ float r[256];
    r[tid] = s; __syncthreads();
    for (int st = blockDim.x >> 1; st > 0; st >>= 1) { if (tid < st) r[tid] += r[tid + st]; __syncthreads(); }
    if (tid == 0) out[i] = r[0];
}

__global__ void normalize_rows(const float* __restrict__ X, float* __restrict__ Y, int D)
{
    int i = blockIdx.x, tid = threadIdx.x;
    float s = 0.f;
    for (int j = tid; j < D; j += blockDim.x) { float v = X[(size_t)i*D + j]; s = fmaf(v, v, s); }
    __shared__ float r[256];
    r[tid] = s; __syncthreads();
    for (int st = blockDim.x >> 1; st > 0; st >>= 1) { if (tid < st) r[tid] += r[tid + st]; __syncthreads(); }
    float nrm = sqrtf(r[0]);
    for (int j = tid; j < D; j += blockDim.x) Y[(size_t)i*D + j] = X[(size_t)i*D + j] / nrm;
}

// ---------------- deterministic total order: (value desc, index asc) ----------------
__device__ __forceinline__ bool better(float a, int ai, float b, int bi)
{
    return (a > b) || (a == b && ai < bi);
}

// ---------------- single-pass top-6, z-batched ----------------
// Each of 128 threads keeps a local insertion-sorted top-6 over its strided slice,
// then 6 exclusion-argmax passes over the 768 candidates. Selection identical to
// 6 global argmax passes under the same total order.
__global__ void top6_onepass(const float* __restrict__ S0, const float* __restrict__ S1,
                             int* __restrict__ oI0, float* __restrict__ oV0,
                             int* __restrict__ oI1, float* __restrict__ oV1)
{
    const float* S = blockIdx.z ? S1 : S0;
    int*   oI = blockIdx.z ? oI1 : oI0;
    float* oV = blockIdx.z ? oV1 : oV0;

    __shared__ float sv[128*TOPK];
    __shared__ int   si[128*TOPK];
    __shared__ int   ch[TOPK];
    __shared__ float rv[128];
    __shared__ int   ri[128];

    int row = blockIdx.x, tid = threadIdx.x;
    const float* Sr = S + (size_t)row * NN;

    float lv[TOPK]; int li[TOPK];
#pragma unroll
    for (int t = 0; t < TOPK; t++) { lv[t] = -FLT_MAX; li[t] = 0x7FFFFFFF; }
    for (int j = tid; j < NN; j += 128) {
        float x = Sr[j];
        if (better(x, j, lv[TOPK-1], li[TOPK-1])) {
            lv[TOPK-1] = x; li[TOPK-1] = j;
#pragma unroll
            for (int t = TOPK-1; t > 0; t--) {
                if (better(lv[t], li[t], lv[t-1], li[t-1])) {
                    float tv = lv[t]; lv[t] = lv[t-1]; lv[t-1] = tv;
                    int ti = li[t]; li[t] = li[t-1]; li[t-1] = ti;
                } else break;
            }
        }
    }
#pragma unroll
    for (int t = 0; t < TOPK; t++) { sv[tid*TOPK+t] = lv[t]; si[tid*TOPK+t] = li[t]; }
    __syncthreads();

    for (int t = 0; t < TOPK; t++) {
        float bv = -FLT_MAX; int bi = 0x7FFFFFFF;
#pragma unroll
        for (int u = 0; u < TOPK; u++) {
            int e = tid*TOPK + u;
            int cidx = si[e];
            bool used = false;
            for (int w = 0; w < t; w++) used |= (ch[w] == cidx);
            if (!used && better(sv[e], cidx, bv, bi)) { bv = sv[e]; bi = cidx; }
        }
        rv[tid] = bv; ri[tid] = bi;
        __syncthreads();
        if (tid < 32) {
#pragma unroll
            for (int o = 32; o < 128; o += 32) {
                if (better(rv[tid+o], ri[tid+o], bv, bi)) { bv = rv[tid+o]; bi = ri[tid+o]; }
            }
#pragma unroll
            for (int o = 16; o > 0; o >>= 1) {
                float ov = __shfl_down_sync(0xFFFFFFFFu, bv, o);
                int   oi = __shfl_down_sync(0xFFFFFFFFu, bi, o);
                if (better(ov, oi, bv, bi)) { bv = ov; bi = oi; }
            }
            if (tid == 0) {
                ch[t] = bi;
                oI[row*TOPK + t] = bi;
                oV[row*TOPK + t] = bv;
            }
        }
        __syncthreads();
    }
}

// ---------------- adjacency mask build, z-batched ----------------
__global__ void clear_masks()
{
    int i = blockIdx.x * blockDim.x + threadIdx.x;   // NN*NN/4 words
    ((unsigned int*)g_maskU)[i] = 0u;
    ((unsigned int*)g_maskF)[i] = 0u;
}

__global__ void mark_kernel2(const int* __restrict__ idx0, const float* __restrict__ val0,
                             unsigned char* __restrict__ mask0,
                             const int* __restrict__ idx1, const float* __restrict__ val1,
                             unsigned char* __restrict__ mask1)
{
    const int*   idx  = blockIdx.z ? idx1 : idx0;
    const float* val  = blockIdx.z ? val1 : val0;
    unsigned char* mask = blockIdx.z ? mask1 : mask0;
    int needPos = blockIdx.z;   // food (z=1) requires positive sim
    int i = blockIdx.x * blockDim.x + threadIdx.x;
    if (i >= NN) return;
#pragma unroll
    for (int t = 0; t < TOPK; t++) {
        int j = idx[i*TOPK + t];
        if (j == i) continue;
        if (needPos && !(val[i*TOPK + t] > 0.f)) continue;
        mask[(size_t)i*NN + j] = 1;
        mask[(size_t)j*NN + i] = 1;
    }
}

// ---------------- neighbor list: warp-ballot compaction (ascending), z-batched ----------------
__global__ void collect_kernel2(const unsigned char* __restrict__ mask0,
                                int* __restrict__ nbr0, int* __restrict__ cnt0,
                                const unsigned char* __restrict__ mask1,
                                int* __restrict__ nbr1, int* __restrict__ cnt1)
{
    const unsigned char* mask = blockIdx.z ? mask1 : mask0;
    int* nbr = blockIdx.z ? nbr1 : nbr0;
    int* cnt = blockIdx.z ? cnt1 : cnt0;
    int warp = (blockIdx.x * blockDim.x + threadIdx.x) >> 5;
    int lane = threadIdx.x & 31;
    if (warp >= NN) return;
    const unsigned char* mr = mask + (size_t)warp * NN;
    int c = 0;
    for (int base = 0; base < NN; base += 32) {
        bool m = mr[base + lane] != 0;
        unsigned b = __ballot_sync(0xFFFFFFFFu, m);
        if (m) nbr[(size_t)warp*MAXD + c + __popc(b & ((1u << lane) - 1u))] = base + lane;
        c += __popc(b);
    }
    if (lane == 0) cnt[warp] = c;
}

// ---------------- sparse attention + aggregate + elu (hub-safe, PROVEN), z-batched ----------------
__global__ void att_agg2(const float* __restrict__ Wh0, const float* __restrict__ s10,
                         const float* __restrict__ s20, const int* __restrict__ nbr0,
                         const int* __restrict__ cnt0, float* __restrict__ out0,
                         const float* __restrict__ Wh1, const float* __restrict__ s11,
                         const float* __restrict__ s21, const int* __restrict__ nbr1,
                         const int* __restrict__ cnt1, float* __restrict__ out1,
                         int rowStride, int nheads)
{
    const float* Wh = blockIdx.z ? Wh1 : Wh0;
    const float* s1 = blockIdx.z ? s11 : s10;
    const float* s2 = blockIdx.z ? s21 : s20;
    const int* nbr  = blockIdx.z ? nbr1 : nbr0;
    const int* cnt  = blockIdx.z ? cnt1 : cnt0;
    float* out      = blockIdx.z ? out1 : out0;

    __shared__ int   sidx[MAXD];       // 8 KB
    __shared__ float sw[NH][MAXD];     // 32 KB
    __shared__ float hs[NH];
    int i = blockIdx.x, tid = threadIdx.x;
    int wid = tid >> 5, lane = tid & 31;
    int c = cnt[i];

    for (int t = tid; t < c; t += 256) sidx[t] = nbr[(size_t)i*MAXD + t];
    __syncthreads();

    for (int q = tid; q < nheads*c; q += 256) {
        int h = q / c, t = q - h*c;
        float e = s1[h*NN + i] + s2[h*NN + sidx[t]];
        sw[h][t] = (e >= 0.f) ? e : 0.2f * e;
    }
    __syncthreads();

    if (wid < nheads) {
        int h = wid;
        float m = -FLT_MAX;
        for (int t = lane; t < c; t += 32) m = fmaxf(m, sw[h][t]);
#pragma unroll
        for (int o = 16; o > 0; o >>= 1) m = fmaxf(m, __shfl_xor_sync(0xFFFFFFFFu, m, o));
        float s = 0.f;
        for (int t = lane; t < c; t += 32) { float ex = expf(sw[h][t] - m); sw[h][t] = ex; s += ex; }
#pragma unroll
        for (int o = 16; o > 0; o >>= 1) s += __shfl_xor_sync(0xFFFFFFFFu, s, o);
        if (lane == 0) hs[h] = s;
    }
    __syncthreads();

    for (int q = tid; q < nheads*c; q += 256) {
        int h = q / c, t = q - h*c;
        sw[h][t] /= hs[h];
    }
    __syncthreads();

    for (int h = 0; h < nheads; h++) {
        float acc = 0.f;
#pragma unroll 4
        for (int t = 0; t < c; t++)
            acc = fmaf(sw[h][t], Wh[(size_t)sidx[t]*rowStride + h*HID + tid], acc);
        out[(size_t)i*rowStride + h*HID + tid] = (acc > 0.f) ? acc : expm1f(acc);
    }
}

// ---------------- GAT helper kernels, z-batched ----------------
__global__ void repack_W2(const float* __restrict__ W0, float* __restrict__ Wcat0,
                          const float* __restrict__ W1, float* __restrict__ Wcat1)
{
    const float* W = blockIdx.z ? W1 : W0;
    float* Wcat    = blockIdx.z ? Wcat1 : Wcat0;
    int i = blockIdx.x * blockDim.x + threadIdx.x;
    if (i >= DIN*NH*HID) return;
    int d = i / (NH*HID);
    int r = i % (NH*HID);
    int h = r / HID;
    int f = r % HID;
    Wcat[i] = W[(size_t)h*DIN*HID + (size_t)d*HID + f];
}

__global__ void s1s2_kernel2(const float* __restrict__ WhA, const float* __restrict__ aA,
                             float* __restrict__ s1A, float* __restrict__ s2A,
                             const float* __restrict__ WhB, const float* __restrict__ aB,
                             float* __restrict__ s1B, float* __restrict__ s2B,
                             int rowStride)
{
    const float* Wh = blockIdx.z ? WhB : WhA;
    const float* a  = blockIdx.z ? aB : aA;
    float* s1 = blockIdx.z ? s1B : s1A;
    float* s2 = blockIdx.z ? s2B : s2A;
    int i = blockIdx.x, h = blockIdx.y, f = threadIdx.x;   // 256 threads
    float w = Wh[(size_t)i*rowStride + h*HID + f];
    float v1 = w * a[h*2*HID + f];
    float v2 = w * a[h*2*HID + HID + f];
    __shared__ float r1[256], r2[256];
    r1[f] = v1; r2[f] = v2; __syncthreads();
    for (int st = 128; st > 0; st >>= 1) {
        if (f < st) { r1[f] += r1[f+st]; r2[f] += r2[f+st]; }
        __syncthreads();
    }
    if (f == 0) { s1[h*NN + i] = r1[0]; s2[h*NN + i] = r2[0]; }
}

// ---------------- MLP pieces (PROVEN) ----------------
__global__ void concat_kernel()
{
    int i = blockIdx.x, c = threadIdx.x;   // 512 threads
    g_pair[(size_t)i*512 + c] = (c < HID) ? g_embU[(size_t)i*HID + c]
                                          : g_embF[(size_t)i*HID + (c - HID)];
}

__global__ void mlp_final_kernel(const float* __restrict__ act, const float* __restrict__ W,
                                 const float* __restrict__ b, float* __restrict__ out)
{
    int i = blockIdx.x, tid = threadIdx.x;   // 128 threads
    float v = act[(size_t)i*128 + tid] * W[tid];
    __shared__ float r[128];
    r[tid] = v; __syncthreads();
    for (int st = 64; st > 0; st >>= 1) { if (tid < st) r[tid] += r[tid+st]; __syncthreads(); }
    if (tid == 0) out[i] = r[0] + b[0];
}

// ---------------- host launch ----------------
template <typename T>
static T* sym(const void* s)
{
    void* p = nullptr;
    cudaGetSymbolAddress(&p, s);
    return (T*)p;
}

extern "C" void kernel_launch(void* const* d_in, const int* in_sizes, int n_in,
                              void* d_out, int out_size)
{
    const float* user_nodes = (const float*)d_in[0];
    const float* food_nodes = (const float*)d_in[1];
    const float* user_W_h   = (const float*)d_in[2];
    const float* user_a_h   = (const float*)d_in[3];
    const float* user_W_o   = (const float*)d_in[4];
    const float* user_a_o   = (const float*)d_in[5];
    const float* food_W_h   = (const float*)d_in[6];
    const float* food_a_h   = (const float*)d_in[7];
    const float* food_W_o   = (const float*)d_in[8];
    const float* food_a_o   = (const float*)d_in[9];
    const float* mlp_W0 = (const float*)d_in[10];
    const float* mlp_b0 = (const float*)d_in[11];
    const float* mlp_W1 = (const float*)d_in[12];
    const float* mlp_b1 = (const float*)d_in[13];
    const float* mlp_W2 = (const float*)d_in[14];
    const float* mlp_b2 = (const float*)d_in[15];
    const float* mlp_W3 = (const float*)d_in[16];
    const float* mlp_b3 = (const float*)d_in[17];
    float* out = (float*)d_out;

    float* pZero  = sym<float>(g_zero);
    float* pSqU   = sym<float>(g_sqU);
    float* pXnF   = sym<float>(g_XnF);
    float* pSimU  = sym<float>(g_simU);
    float* pSimF  = sym<float>(g_simF);
    int*   pTidxU = sym<int>(g_tidxU);
    float* pTvalU = sym<float>(g_tvalU);
    int*   pTidxF = sym<int>(g_tidxF);
    float* pTvalF = sym<float>(g_tvalF);
    unsigned char* pMaskU = sym<unsigned char>(g_maskU);
    unsigned char* pMaskF = sym<unsigned char>(g_maskF);
    int*   pNbrU = sym<int>(g_nbrU);
    int*   pCntU = sym<int>(g_cntU);
    int*   pNbrF = sym<int>(g_nbrF);
    int*   pCntF = sym<int>(g_cntF);
    float* pWcatU = sym<float>(g_WcatU);
    float* pWcatF = sym<float>(g_WcatF);
    float* pWhU  = sym<float>(g_WhU);
    float* pWhF  = sym<float>(g_WhF);
    float* pS1U  = sym<float>(g_s1U);
    float* pS2U  = sym<float>(g_s2U);
    float* pS1F  = sym<float>(g_s1F);
    float* pS2F  = sym<float>(g_s2F);
    float* pHidU = sym<float>(g_hidU);
    float* pHidF = sym<float>(g_hidF);
    float* pWhoU = sym<float>(g_WhoU);
    float* pWhoF = sym<float>(g_WhoF);
    float* pS1oU = sym<float>(g_s1oU);
    float* pS2oU = sym<float>(g_s2oU);
    float* pS1oF = sym<float>(g_s1oF);
    float* pS2oF = sym<float>(g_s2oF);
    float* pEmbU = sym<float>(g_embU);
    float* pEmbF = sym<float>(g_embF);
    float* pPair = sym<float>(g_pair);
    float* pAct0 = sym<float>(g_act0);
    float* pAct1 = sym<float>(g_act1);
    float* pAct2 = sym<float>(g_act2);

    const int NTRI = (NN/128) * (NN/128 + 1) / 2;   // 136 upper-tri tiles

    // ---- graph build ----
    rowsum_sq<<<NN, 256>>>(user_nodes, pSqU, DIN);
    normalize_rows<<<NN, 256>>>(food_nodes, pXnF, DIN);
    // batched sims: z=0 user euclid (-d^2), z=1 food cosine scaled by exact 2x (sq=0)
    sgemm2<true, 1, true, 128,128,8,8><<<dim3(NTRI,1,2), 256>>>(
        user_nodes, user_nodes, pSimU, pSqU, nullptr,
        pXnF,       pXnF,       pSimF, pZero, nullptr,
        NN, NN, DIN, DIN, DIN, NN);
    top6_onepass<<<dim3(NN,1,2), 128>>>(pSimU, pSimF, pTidxU, pTvalU, pTidxF, pTvalF);

    clear_masks<<<(NN*NN/4)/256, 256>>>();
    mark_kernel2<<<dim3((NN+255)/256,1,2), 256>>>(pTidxU, pTvalU, pMaskU,
                                                  pTidxF, pTvalF, pMaskF);
    collect_kernel2<<<dim3(NN*32/256,1,2), 256>>>(pMaskU, pNbrU, pCntU,
                                                  pMaskF, pNbrF, pCntF);

    // ---- GAT hidden layer (user & food batched) ----
    repack_W2<<<dim3((DIN*NH*HID+255)/256,1,2), 256>>>(user_W_h, pWcatU, food_W_h, pWcatF);
    sgemm2<false, 0, false, 128,128,8,8><<<dim3((NH*HID)/128, NN/128, 2), 256>>>(
        user_nodes, pWcatU, pWhU, nullptr, nullptr,
        food_nodes, pWcatF, pWhF, nullptr, nullptr,
        NN, NH*HID, DIN, DIN, NH*HID, NH*HID);
    s1s2_kernel2<<<dim3(NN, NH, 2), 256>>>(pWhU, user_a_h, pS1U, pS2U,
                                           pWhF, food_a_h, pS1F, pS2F, NH*HID);
    att_agg2<<<dim3(NN,1,2), 256>>>(pWhU, pS1U, pS2U, pNbrU, pCntU, pHidU,
                                    pWhF, pS1F, pS2F, pNbrF, pCntF, pHidF,
                                    NH*HID, NH);

    // ---- GAT output layer (user & food batched) ----
    sgemm2<false, 0, false, 64,64,4,4><<<dim3(HID/64, NN/64, 2), 256>>>(
        pHidU, user_W_o, pWhoU, nullptr, nullptr,
        pHidF, food_W_o, pWhoF, nullptr, nullptr,
        NN, HID, NH*HID, NH*HID, HID, HID);
    s1s2_kernel2<<<dim3(NN, 1, 2), 256>>>(pWhoU, user_a_o, pS1oU, pS2oU,
                                          pWhoF, food_a_o, pS1oF, pS2oF, HID);
    att_agg2<<<dim3(NN,1,2), 256>>>(pWhoU, pS1oU, pS2oU, pNbrU, pCntU, pEmbU,
                                    pWhoF, pS1oF, pS2oF, pNbrF, pCntF, pEmbF,
                                    HID, 1);

    // ---- MLP ----
    concat_kernel<<<NN, 512>>>();
    sgemm2<false, 2, false, 64,64,4,4><<<dim3(512/64, NN/64, 1), 256>>>(
        pPair, mlp_W0, pAct0, nullptr, mlp_b0,
        pPair, mlp_W0, pAct0, nullptr, mlp_b0,
        NN, 512, 512, 512, 512, 512);
    sgemm2<false, 2, false, 64,64,4,4><<<dim3(256/64, NN/64, 1), 256>>>(
        pAct0, mlp_W1, pAct1, nullptr, mlp_b1,
        pAct0, mlp_W1, pAct1, nullptr, mlp_b1,
        NN, 256, 512, 512, 256, 256);
    sgemm2<false, 2, false, 64,64,4,4><<<dim3(128/64, NN/64, 1), 256>>>(
        pAct1, mlp_W2, pAct2, nullptr, mlp_b2,
        pAct1, mlp_W2, pAct2, nullptr, mlp_b2,
        NN, 128, 256, 256, 128, 128);
    mlp_final_kernel<<<NN, 128>>>(pAct2, mlp_W3, mlp_b3, out);
}